// round 16
// baseline (speedup 1.0000x reference)
#include <cuda_runtime.h>
#include <cuda_fp16.h>
#include <cstdint>

#define GN 2048
#define GB 16
typedef __half half_t;

// ---------------- scratch ----------------
// Activations: 64ch-blocked NC, swizzled rows: X[b][cb][n][64]
__device__ __align__(16) half_t g_E1[(size_t)GB*2*GN*64];
__device__ __align__(16) half_t g_H [(size_t)GB*2*GN*64];
__device__ __align__(16) half_t g_M [(size_t)GB*2*GN*64];
__device__ __align__(16) half_t g_T [(size_t)GB*2*GN*64];       // blocked, like others
__device__ __align__(16) half_t g_XC[(size_t)GB*6*GN*64];
__device__ __align__(16) half_t g_XF[(size_t)GB*16*GN*64];
__device__ __align__(16) half_t g_C1[(size_t)GB*8*GN*64];
__device__ __align__(16) half_t g_C2[(size_t)GB*4*GN*64];
__device__ int   g_IDX [GB*GN*16];
__device__ float g_RMAX[GB*1024], g_RAVG[GB*1024], g_B1[GB*512];
// blocked fp16 weights [otile64][kb][64][64] swizzled (4096 halves / block)
__device__ __align__(16) half_t g_We2[16384];
__device__ __align__(16) half_t g_W1 [49152];
__device__ __align__(16) half_t g_W2 [49152];
__device__ __align__(16) half_t g_Wf [393216];
__device__ __align__(16) half_t g_Wc1[524288];
__device__ __align__(16) half_t g_Wc2[131072];
__device__ __align__(16) half_t g_Wc3[16384];

// swizzle within a 128B row: XOR 16B-group index with (row&7)
__device__ __forceinline__ int swz(int row, int byteInRow) {
    return byteInRow ^ ((row & 7) << 4);
}

// ---------------- weight fp32 -> blocked swizzled fp16 (64-row tiles) ----------
struct CwSeg { const float* src; half_t* dst; int O, K, wS, nKb, blkStart; };
struct CwArgs { CwSeg s[7]; int totalBlks; };
__global__ void convw_blk(CwArgs a)
{
    int id = blockIdx.x * 256 + threadIdx.x;
    int blk = id >> 12;
    if (blk >= a.totalBlks) return;
    int si = 0;
    while (si < 6 && blk >= a.s[si + 1].blkStart) ++si;
    const CwSeg S = a.s[si];
    int bloc = blk - S.blkStart;
    int rem = id & 4095;
    int r = rem >> 6, ci = rem & 63;
    int ot = bloc / S.nKb, kb = bloc % S.nKb;
    int o = ot * 64 + r, k = kb * 64 + ci;
    float v = (o < S.O) ? S.src[(size_t)o * S.wS + k] : 0.f;
    S.dst[(size_t)bloc * 4096 + r * 64 + (swz(r, ci * 2) >> 1)] = __float2half_rn(v);
}

// ---------------- KNN ----------------
__global__ void knn_kernel(const float* __restrict__ pts, int* __restrict__ idxout)
{
    __shared__ float4 tile[256];
    int b = blockIdx.x;
    int n = blockIdx.y * 128 + threadIdx.x;
    const float* pb = pts + (long long)b * 6 * GN;
    float px = pb[n], py = pb[GN + n], pz = pb[2 * GN + n];
    float sp = px * px + py * py + pz * pz;
    float best[16]; int bidx[16];
#pragma unroll
    for (int i = 0; i < 16; ++i) { best[i] = 3.4e38f; bidx[i] = 0; }
    for (int t0 = 0; t0 < GN; t0 += 256) {
        __syncthreads();
        for (int i = threadIdx.x; i < 256; i += 128) {
            int m = t0 + i;
            float qx = pb[m], qy = pb[GN + m], qz = pb[2 * GN + m];
            tile[i] = make_float4(qx, qy, qz, qx * qx + qy * qy + qz * qz);
        }
        __syncthreads();
        for (int i = 0; i < 256; ++i) {
            float4 q = tile[i];
            float d = sp + q.w - 2.0f * (px * q.x + py * q.y + pz * q.z);
            if (d < best[15]) {
                int cand = t0 + i, pos = 0;
#pragma unroll
                for (int k = 0; k < 16; ++k) pos += (best[k] <= d);
#pragma unroll
                for (int k = 15; k > 0; --k)
                    if (k > pos) { best[k] = best[k - 1]; bidx[k] = bidx[k - 1]; }
#pragma unroll
                for (int k = 0; k < 16; ++k)
                    if (k == pos) { best[k] = d; bidx[k] = cand; }
            }
        }
    }
    int* op = idxout + ((long long)b * GN + n) * 16;
#pragma unroll
    for (int i = 0; i < 16; ++i) op[i] = bidx[i];
}

// ---------------- e1 -> blocked layout ----------------
__global__ void e1_kernel(const float* __restrict__ pts, const float* __restrict__ W,
                          const float* __restrict__ g, const float* __restrict__ bb,
                          half_t* __restrict__ out)
{
    __shared__ float Wsh[768], gs[128], bs[128];
    int b = blockIdx.x, tid = threadIdx.x;
    int n = blockIdx.y * 256 + tid;
    for (int i = tid; i < 768; i += 256) Wsh[i] = W[i];
    if (tid < 128) { gs[tid] = g[tid]; bs[tid] = bb[tid]; }
    __syncthreads();
    float x[6];
#pragma unroll
    for (int c = 0; c < 6; ++c) x[c] = pts[((long long)b * 6 + c) * GN + n];
    for (int c8 = 0; c8 < 128; c8 += 8) {
        __align__(16) half_t h8[8];
#pragma unroll
        for (int q = 0; q < 8; ++q) {
            int o = c8 + q;
            float s = 0.f;
#pragma unroll
            for (int c = 0; c < 6; ++c) s += Wsh[o * 6 + c] * x[c];
            s = fmaxf(s * gs[o] + bs[o], 0.f);
            h8[q] = __float2half_rn(s);
        }
        int cb = c8 >> 6;
        int gpos = ((c8 >> 3) & 7) ^ (n & 7);
        *(uint4*)(out + (((size_t)b * 2 + cb) * GN + n) * 64 + gpos * 8) = *(uint4*)h8;
    }
}

// ---------------- GEMM: bulk-fed, 128n x 64o tiles, 4 CTAs/SM, 2-stage ----------
struct GemmArgs {
    const half_t* Wp;
    int O, K;
    const half_t* Bx; int aCb, aCbOff;
    half_t* Y; int yCbTot, yCbOff;
    float* oF; int oFC;
    const float *pre, *g, *post, *postB;
    const half_t* R; int rCbTot, rCbOff;
    int act;
};

__device__ __forceinline__ uint32_t s2u(const void* p) {
    return (uint32_t)__cvta_generic_to_shared(p);
}
__device__ __forceinline__ void ldm4(uint32_t* r, uint32_t a) {
    asm volatile("ldmatrix.sync.aligned.m8n8.x4.shared.b16 {%0,%1,%2,%3},[%4];\n"
                 : "=r"(r[0]), "=r"(r[1]), "=r"(r[2]), "=r"(r[3]) : "r"(a));
}
__device__ __forceinline__ void mma16816(float* d, const uint32_t* A, uint32_t b0, uint32_t b1) {
    asm volatile(
        "mma.sync.aligned.m16n8k16.row.col.f32.f16.f16.f32 "
        "{%0,%1,%2,%3},{%4,%5,%6,%7},{%8,%9},{%0,%1,%2,%3};\n"
        : "+f"(d[0]), "+f"(d[1]), "+f"(d[2]), "+f"(d[3])
        : "r"(A[0]), "r"(A[1]), "r"(A[2]), "r"(A[3]), "r"(b0), "r"(b1));
}
__device__ __forceinline__ void wait_par(uint32_t mbar, int ph) {
    asm volatile(
        "{\n\t.reg .pred P1;\n\tWL_%=:\n\t"
        "mbarrier.try_wait.parity.acquire.cta.shared::cta.b64 P1,[%0],%1,0x989680;\n\t"
        "@P1 bra WD_%=;\n\tbra WL_%=;\n\tWD_%=:\n\t}"
        :: "r"(mbar), "r"((uint32_t)ph) : "memory");
}
__device__ __forceinline__ void bulk_ld(uint32_t dst, const void* src, uint32_t bytes, uint32_t mbar) {
    asm volatile("cp.async.bulk.shared::cluster.global.mbarrier::complete_tx::bytes [%0],[%1],%2,[%3];\n"
                 :: "r"(dst), "l"(src), "r"(bytes), "r"(mbar) : "memory");
}
__device__ __forceinline__ void bulk_st(void* dst, uint32_t src, uint32_t bytes) {
    asm volatile("cp.async.bulk.global.shared::cta.bulk_group [%0],[%1],%2;\n"
                 :: "l"(dst), "r"(src), "r"(bytes) : "memory");
}

// smem: [0..1024) ctrl, then 2 stages x 24KB (ACT 16KB + WT 8KB) = 50.2KB -> 4 CTAs/SM
#define STG_BYTES 24576
#define SMEM_GEMM (1024 + 2 * STG_BYTES)

__global__ void __launch_bounds__(256, 4) gemm_mma(GemmArgs P)
{
    extern __shared__ char sm[];
    const uint32_t smb = s2u(sm);
    const int tid = threadIdx.x, lane = tid & 31, wid = tid >> 5;
    const int wn = wid & 3, wo = wid >> 2;       // warp tile: 32n x 32o
    const int b = blockIdx.z, n0 = blockIdx.x * 128, o0 = blockIdx.y * 64;
    const int nch = P.K >> 6;

    if (tid == 0) {
#pragma unroll
        for (int s = 0; s < 2; ++s)
            asm volatile("mbarrier.init.shared.b64 [%0],1;" :: "r"(smb + s * 8) : "memory");
    }
    __syncthreads();

    auto issueChunk = [&](int c) {
        if (tid == 0) {
            int s = c & 1;
            uint32_t mbar = smb + s * 8;
            asm volatile("mbarrier.arrive.expect_tx.shared.b64 _,[%0],%1;"
                         :: "r"(mbar), "r"((uint32_t)STG_BYTES) : "memory");
            uint32_t st = smb + 1024 + s * STG_BYTES;
            const half_t* asrc = P.Bx + (((size_t)b * P.aCb + P.aCbOff + c) * GN + n0) * 64;
            bulk_ld(st, asrc, 16384, mbar);
            const half_t* wsrc = P.Wp + ((size_t)blockIdx.y * nch + c) * 4096;
            bulk_ld(st + 16384, wsrc, 8192, mbar);
        }
    };

    float acc[2][4][4];
#pragma unroll
    for (int i = 0; i < 2; ++i)
#pragma unroll
        for (int j = 0; j < 4; ++j)
#pragma unroll
            for (int k = 0; k < 4; ++k) acc[i][j][k] = 0.f;

    issueChunk(0);
    if (nch > 1) issueChunk(1);

    const int rowIn16 = (lane & 7) + ((lane >> 3) & 1) * 8;
    const int colB = (lane >> 4) << 4;
    int ph[2] = {0, 0};

    for (int c = 0; c < nch; ++c) {
        int s = c & 1;
        wait_par(smb + s * 8, ph[s]);
        ph[s] ^= 1;
        uint32_t actB = smb + 1024 + s * STG_BYTES;
        uint32_t wtB = actB + 16384;
#pragma unroll
        for (int ks = 0; ks < 4; ++ks) {
            uint32_t bw[2][4];
#pragma unroll
            for (int j = 0; j < 2; ++j) {
                int row = wo * 32 + j * 16 + rowIn16;
                ldm4(bw[j], wtB + (uint32_t)(row * 128 + swz(row, ks * 32 + colB)));
            }
#pragma unroll
            for (int mt = 0; mt < 2; ++mt) {
                uint32_t aF[4];
                int row = wn * 32 + mt * 16 + rowIn16;
                ldm4(aF, actB + (uint32_t)(row * 128 + swz(row, ks * 32 + colB)));
#pragma unroll
                for (int j = 0; j < 2; ++j) {
                    mma16816(acc[mt][2 * j],     aF, bw[j][0], bw[j][2]);
                    mma16816(acc[mt][2 * j + 1], aF, bw[j][1], bw[j][3]);
                }
            }
        }
        __syncthreads();
        if (c + 2 < nch) issueChunk(c + 2);
    }

    // ---- epilogue ----
    const int q = lane >> 2, tcol = (lane & 3) * 2;
    half_t* sY = (half_t*)(sm + 1024);            // 16KB staging (stage 0 area)

#pragma unroll
    for (int mt = 0; mt < 2; ++mt) {
#pragma unroll
        for (int ot = 0; ot < 4; ++ot) {
            int ol = wo * 32 + ot * 8 + tcol;
            int o = o0 + ol;
            bool ok = (o < P.O);
            float pr0 = 0, pr1 = 0, g0 = 1, g1 = 1, po0 = 0, po1 = 0;
            if (ok) {
                if (P.pre) { pr0 = P.pre[o]; pr1 = P.pre[o + 1]; }
                if (P.g) { g0 = P.g[o]; g1 = P.g[o + 1]; }
                if (P.post) { po0 = P.post[o]; po1 = P.post[o + 1]; }
                if (P.postB) { po0 += P.postB[b * P.O + o]; po1 += P.postB[b * P.O + o + 1]; }
            }
#pragma unroll
            for (int hh = 0; hh < 2; ++hh) {
                int nl = wn * 32 + mt * 16 + q + hh * 8;
                int n = n0 + nl;
                float v0 = (acc[mt][ot][hh * 2 + 0] + pr0) * g0 + po0;
                float v1 = (acc[mt][ot][hh * 2 + 1] + pr1) * g1 + po1;
                if (P.R) {
                    int och = o0 + ol;
                    size_t rrow = ((size_t)b * P.rCbTot + P.rCbOff + (och >> 6)) * GN + n;
                    int ci = och & 63;
                    const __half2 r2 = *(const __half2*)(P.R + rrow * 64 + (swz(n, ci * 2) >> 1));
                    float2 rf = __half22float2(r2);
                    v0 += rf.x; v1 += rf.y;
                }
                if (P.act == 1) { v0 = fmaxf(v0, 0.f); v1 = fmaxf(v1, 0.f); }
                else if (P.act == 2) { v0 = v0 > 0.f ? v0 : 0.2f * v0; v1 = v1 > 0.f ? v1 : 0.2f * v1; }
                if (P.Y) {
                    __half2 hp = __floats2half2_rn(v0, v1);
                    *(__half2*)(sY + nl * 64 + (swz(nl, ol * 2) >> 1)) = hp;
                }
                if (P.oF && ok) {
                    P.oF[((size_t)b * P.oFC + o) * GN + n] = v0;
                    if (o + 1 < P.O) P.oF[((size_t)b * P.oFC + o + 1) * GN + n] = v1;
                }
            }
        }
    }
    if (P.Y) {
        __syncthreads();
        asm volatile("fence.proxy.async.shared::cta;" ::: "memory");
        if (tid == 0) {
            bulk_st(P.Y + (((size_t)b * P.yCbTot + P.yCbOff + (o0 >> 6)) * GN + n0) * 64,
                    s2u(sY), 16384);
            asm volatile("cp.async.bulk.commit_group;\n" ::: "memory");
            asm volatile("cp.async.bulk.wait_group 0;\n" ::: "memory");
        }
    }
}

// ---------------- gather + max (T blocked -> M blocked) ----------------
__global__ void gathermax_kernel(const half_t* __restrict__ T, const int* __restrict__ IDX,
                                 half_t* __restrict__ M)
{
    int b = blockIdx.x;
    int w = threadIdx.x >> 5, l = threadIdx.x & 31;
    int n = blockIdx.y * 8 + w;
    const int* ib = IDX + ((size_t)b * GN + n) * 16;
    int ch0 = l * 4, cb = ch0 >> 6, ci = ch0 & 63;
    const half_t* tb = T + ((size_t)b * 2 + cb) * GN * 64;
    float4 best = make_float4(-3.4e38f, -3.4e38f, -3.4e38f, -3.4e38f);
#pragma unroll
    for (int k = 0; k < 16; ++k) {
        int j = ib[k];
        uint2 u = *(const uint2*)(tb + (size_t)j * 64 + (swz(j, ci * 2) >> 1));
        float2 a = __half22float2(*(__half2*)&u.x);
        float2 c = __half22float2(*(__half2*)&u.y);
        best.x = fmaxf(best.x, a.x); best.y = fmaxf(best.y, a.y);
        best.z = fmaxf(best.z, c.x); best.w = fmaxf(best.w, c.y);
    }
    __align__(8) half_t h4[4];
    h4[0] = __float2half_rn(best.x); h4[1] = __float2half_rn(best.y);
    h4[2] = __float2half_rn(best.z); h4[3] = __float2half_rn(best.w);
    *(uint2*)(M + (((size_t)b * 2 + cb) * GN + n) * 64 + (swz(n, ci * 2) >> 1)) = *(uint2*)h4;
}

// ---------------- reduce over points for XF (blocked) ----------------
__global__ void reduce_kernel(const half_t* __restrict__ XF,
                              float* __restrict__ RMAX, float* __restrict__ RAVG)
{
    __shared__ float smx[8][64], ssm[8][64];
    int b = blockIdx.x, kb = blockIdx.y;
    int t = threadIdx.x;
    int ci = t & 63, g = t >> 6;
    const half_t* base = XF + ((size_t)(b * 16 + kb)) * GN * 64;
    int hpos = swz(g, ci * 2) >> 1;
    float mx = -3.4e38f, sum = 0.f;
    for (int n = g; n < GN; n += 8) {
        float v = __half2float(base[(size_t)n * 64 + hpos]);
        mx = fmaxf(mx, v);
        sum += v;
    }
    smx[g][ci] = mx; ssm[g][ci] = sum;
    __syncthreads();
    if (t < 64) {
        float m = smx[0][t], s = ssm[0][t];
#pragma unroll
        for (int j = 1; j < 8; ++j) { m = fmaxf(m, smx[j][t]); s += ssm[j][t]; }
        RMAX[b * 1024 + kb * 64 + t] = m;
        RAVG[b * 1024 + kb * 64 + t] = s * (1.f / GN);
    }
}

// ---------------- per-batch bias for c1 ----------------
__global__ void bias1_kernel(const float* __restrict__ Wc1, const float* __restrict__ bc1,
                             const float* __restrict__ gc1, const float* __restrict__ bb1,
                             const float* __restrict__ Wl, const float* __restrict__ gl,
                             const float* __restrict__ bl, const float* __restrict__ label,
                             const float* __restrict__ RMAX, const float* __restrict__ RAVG,
                             float* __restrict__ B1)
{
    int b = blockIdx.x;
    int tid = threadIdx.x, warp = tid >> 5, lane = tid & 31;
    __shared__ float lab[64];
    if (tid < 64) {
        float s = 0.f;
#pragma unroll
        for (int i = 0; i < 16; ++i) s += Wl[tid * 16 + i] * label[b * 16 + i];
        s = s * gl[tid] + bl[tid];
        lab[tid] = s > 0.f ? s : 0.2f * s;
    }
    __syncthreads();
    int o = blockIdx.y * 8 + warp;
    const float* wr = Wc1 + (long long)o * 3136;
    const float* xm = RMAX + b * 1024;
    const float* xa = RAVG + b * 1024;
    float s = 0.f;
    for (int j = lane; j < 1024; j += 32)
        s += wr[1024 + j] * xm[j] + wr[2048 + j] * xa[j];
    for (int j = lane; j < 64; j += 32)
        s += wr[3072 + j] * lab[j];
#pragma unroll
    for (int off = 16; off; off >>= 1) s += __shfl_xor_sync(0xffffffffu, s, off);
    if (!lane) B1[b * 512 + o] = gc1[o] * (s + bc1[o]) + bb1[o];
}

// ---------------- host ----------------
template <class T>
static T* symp(const void* s) { void* p = nullptr; cudaGetSymbolAddress(&p, s); return (T*)p; }

static void run_gemm(const half_t* Wp, int O, int K,
                     const half_t* Bx, int aCb, int aCbOff,
                     half_t* Y, int yCbTot, int yCbOff,
                     float* oF, int oFC,
                     const float* pre, const float* g, const float* post, const float* postB,
                     const half_t* R, int rCbTot, int rCbOff, int act)
{
    GemmArgs a;
    a.Wp = Wp; a.O = O; a.K = K; a.Bx = Bx; a.aCb = aCb; a.aCbOff = aCbOff;
    a.Y = Y; a.yCbTot = yCbTot; a.yCbOff = yCbOff;
    a.oF = oF; a.oFC = oFC;
    a.pre = pre; a.g = g; a.post = post; a.postB = postB;
    a.R = R; a.rCbTot = rCbTot; a.rCbOff = rCbOff; a.act = act;
    dim3 grid(GN / 128, (O + 63) / 64, GB);
    gemm_mma<<<grid, 256, SMEM_GEMM>>>(a);
}

extern "C" void kernel_launch(void* const* d_in, const int* in_sizes, int n_in,
                              void* d_out, int out_size)
{
#define FIN(i) ((const float*)d_in[i])
    const float *pts = FIN(0), *label = FIN(1), *We1 = FIN(2), *ge1 = FIN(3), *be1 = FIN(4),
                *We2 = FIN(5), *ge2 = FIN(6), *be2 = FIN(7), *W1 = FIN(8), *g1 = FIN(9),
                *b1 = FIN(10), *W2 = FIN(11), *g2 = FIN(12), *b2 = FIN(13), *Wf = FIN(14),
                *gf = FIN(15), *bf_ = FIN(16), *Wl = FIN(17), *gl = FIN(18), *bl = FIN(19),
                *Wc1 = FIN(20), *bc1 = FIN(21), *gc1 = FIN(22), *bb1 = FIN(23), *Wc2 = FIN(24),
                *bc2 = FIN(25), *gc2 = FIN(26), *bb2 = FIN(27), *Wc3 = FIN(28), *bc3 = FIN(29);
#undef FIN
    float* out = (float*)d_out;

    cudaFuncSetAttribute(gemm_mma, cudaFuncAttributeMaxDynamicSharedMemorySize, SMEM_GEMM);

    half_t *E1 = symp<half_t>(g_E1), *H = symp<half_t>(g_H), *M = symp<half_t>(g_M);
    half_t *T = symp<half_t>(g_T), *XC = symp<half_t>(g_XC), *XF = symp<half_t>(g_XF);
    half_t *C1 = symp<half_t>(g_C1), *C2 = symp<half_t>(g_C2);
    float *RMAX = symp<float>(g_RMAX), *RAVG = symp<float>(g_RAVG), *B1 = symp<float>(g_B1);
    int* IDX = symp<int>(g_IDX);
    half_t *hWe2 = symp<half_t>(g_We2), *hW1 = symp<half_t>(g_W1), *hW2 = symp<half_t>(g_W2);
    half_t *hWf = symp<half_t>(g_Wf), *hWc1 = symp<half_t>(g_Wc1);
    half_t *hWc2 = symp<half_t>(g_Wc2), *hWc3 = symp<half_t>(g_Wc3);

    // launch 0: KNN
    knn_kernel<<<dim3(GB, GN / 128), 128>>>(pts, IDX);
    // launch 1: e1
    e1_kernel<<<dim3(GB, GN / 256), 256>>>(pts, We1, ge1, be1, E1);
    // launch 2: weight conversion (64-row blocks)
    {
        CwArgs a{};
        a.s[0] = {We2, hWe2, 128, 128, 128, 2, 0};
        a.s[1] = {W1,  hW1,  384, 128, 128, 2, 4};
        a.s[2] = {W2,  hW2,  384, 128, 128, 2, 16};
        a.s[3] = {Wf,  hWf, 1024, 384, 384, 6, 28};
        a.s[4] = {Wc1, hWc1, 512, 1024, 3136, 16, 124};
        a.s[5] = {Wc2, hWc2, 256, 512, 512, 8, 252};
        a.s[6] = {Wc3, hWc3, 50, 256, 256, 4, 284};
        a.totalBlks = 288;
        convw_blk<<<(288 * 4096 + 255) / 256, 256>>>(a);
    }
    // launch 3: e2 GEMM  <-- ncu capture slot
    run_gemm(hWe2, 128, 128, E1, 2, 0, H, 2, 0, nullptr, 0,
             nullptr, ge2, be2, nullptr, nullptr, 0, 0, 1);

    // three edge blocks
    const half_t* h = H;
    int hCb = 2, hOff = 0;
    for (int i = 0; i < 3; ++i) {
        // t = relu(bn(W1 h)) -> T (blocked)
        run_gemm(hW1 + (size_t)i * 16384, 128, 128, h, hCb, hOff,
                 T, 2, 0, nullptr, 0,
                 nullptr, g1 + i * 128, b1 + i * 128, nullptr, nullptr, 0, 0, 1);
        gathermax_kernel<<<dim3(GB, GN / 8), 256>>>(T, IDX, M);
        // h = relu(bn(W2 m) + h) -> XC segment i
        run_gemm(hW2 + (size_t)i * 16384, 128, 128, M, 2, 0,
                 XC, 6, i * 2, nullptr, 0,
                 nullptr, g2 + i * 128, b2 + i * 128, nullptr, h, hCb, hOff, 1);
        h = XC; hCb = 6; hOff = i * 2;
    }

    // xf = leaky(bn(Wf @ xcat))
    run_gemm(hWf, 1024, 384, XC, 6, 0, XF, 16, 0, nullptr, 0,
             nullptr, gf, bf_, nullptr, nullptr, 0, 0, 2);

    // global reductions + per-batch bias
    reduce_kernel<<<dim3(GB, 16), 512>>>(XF, RMAX, RAVG);
    bias1_kernel<<<dim3(GB, 64), 256>>>(Wc1, bc1, gc1, bb1, Wl, gl, bl, label,
                                        RMAX, RAVG, B1);

    // c1 = relu(gc1 * Wc1[:, :1024]@xf + per-batch bias)
    run_gemm(hWc1, 512, 1024, XF, 16, 0, C1, 8, 0, nullptr, 0,
             nullptr, gc1, nullptr, B1, nullptr, 0, 0, 1);
    // c2 = relu((Wc2@c1 + bc2)*gc2 + bb2)
    run_gemm(hWc2, 256, 512, C1, 8, 0, C2, 4, 0, nullptr, 0,
             bc2, gc2, bb2, nullptr, nullptr, 0, 0, 1);
    // out = Wc3@c2 + bc3  (fp32 CN)
    run_gemm(hWc3, 50, 256, C2, 4, 0, nullptr, 0, 0, out, 50,
             bc3, nullptr, nullptr, nullptr, nullptr, 0, 0, 0);
}

// round 17
// speedup vs baseline: 1.0692x; 1.0692x over previous
#include <cuda_runtime.h>
#include <cuda_fp16.h>
#include <cstdint>

#define GN 2048
#define GB 16
typedef __half half_t;

// ---------------- scratch ----------------
// Activations: 64ch-blocked NC, swizzled rows: X[b][cb][n][64]
__device__ __align__(16) half_t g_E1[(size_t)GB*2*GN*64];
__device__ __align__(16) half_t g_H [(size_t)GB*2*GN*64];
__device__ __align__(16) half_t g_M [(size_t)GB*2*GN*64];
__device__ __align__(16) half_t g_T [(size_t)GB*2*GN*64];
__device__ __align__(16) half_t g_XC[(size_t)GB*6*GN*64];
__device__ __align__(16) half_t g_XF[(size_t)GB*16*GN*64];
__device__ __align__(16) half_t g_C1[(size_t)GB*8*GN*64];
__device__ __align__(16) half_t g_C2[(size_t)GB*4*GN*64];
__device__ int   g_IDX [GB*GN*16];
__device__ float g_RMAX[GB*1024], g_RAVG[GB*1024], g_B1[GB*512];
__device__ float g_PMX[(size_t)GB*16*1024], g_PSM[(size_t)GB*16*1024];
// blocked fp16 weights [otile64][kb][64][64] swizzled (4096 halves / block)
__device__ __align__(16) half_t g_We2[16384];
__device__ __align__(16) half_t g_W1 [49152];
__device__ __align__(16) half_t g_W2 [49152];
__device__ __align__(16) half_t g_Wf [393216];
__device__ __align__(16) half_t g_Wc1[524288];
__device__ __align__(16) half_t g_Wc2[131072];
__device__ __align__(16) half_t g_Wc3[16384];

// swizzle within a 128B row: XOR 16B-group index with (row&7)
__device__ __forceinline__ int swz(int row, int byteInRow) {
    return byteInRow ^ ((row & 7) << 4);
}

// ---------------- weight fp32 -> blocked swizzled fp16 (64-row tiles) ----------
struct CwSeg { const float* src; half_t* dst; int O, K, wS, nKb, blkStart; };
struct CwArgs { CwSeg s[7]; int totalBlks; };
__global__ void convw_blk(CwArgs a)
{
    int id = blockIdx.x * 256 + threadIdx.x;
    int blk = id >> 12;
    if (blk >= a.totalBlks) return;
    int si = 0;
    while (si < 6 && blk >= a.s[si + 1].blkStart) ++si;
    const CwSeg S = a.s[si];
    int bloc = blk - S.blkStart;
    int rem = id & 4095;
    int r = rem >> 6, ci = rem & 63;
    int ot = bloc / S.nKb, kb = bloc % S.nKb;
    int o = ot * 64 + r, k = kb * 64 + ci;
    float v = (o < S.O) ? S.src[(size_t)o * S.wS + k] : 0.f;
    S.dst[(size_t)bloc * 4096 + r * 64 + (swz(r, ci * 2) >> 1)] = __float2half_rn(v);
}

// ---------------- KNN ----------------
__global__ void knn_kernel(const float* __restrict__ pts, int* __restrict__ idxout)
{
    __shared__ float4 tile[256];
    int b = blockIdx.x;
    int n = blockIdx.y * 128 + threadIdx.x;
    const float* pb = pts + (long long)b * 6 * GN;
    float px = pb[n], py = pb[GN + n], pz = pb[2 * GN + n];
    float sp = px * px + py * py + pz * pz;
    float best[16]; int bidx[16];
#pragma unroll
    for (int i = 0; i < 16; ++i) { best[i] = 3.4e38f; bidx[i] = 0; }
    for (int t0 = 0; t0 < GN; t0 += 256) {
        __syncthreads();
        for (int i = threadIdx.x; i < 256; i += 128) {
            int m = t0 + i;
            float qx = pb[m], qy = pb[GN + m], qz = pb[2 * GN + m];
            tile[i] = make_float4(qx, qy, qz, qx * qx + qy * qy + qz * qz);
        }
        __syncthreads();
        for (int i = 0; i < 256; ++i) {
            float4 q = tile[i];
            float d = sp + q.w - 2.0f * (px * q.x + py * q.y + pz * q.z);
            if (d < best[15]) {
                int cand = t0 + i, pos = 0;
#pragma unroll
                for (int k = 0; k < 16; ++k) pos += (best[k] <= d);
#pragma unroll
                for (int k = 15; k > 0; --k)
                    if (k > pos) { best[k] = best[k - 1]; bidx[k] = bidx[k - 1]; }
#pragma unroll
                for (int k = 0; k < 16; ++k)
                    if (k == pos) { best[k] = d; bidx[k] = cand; }
            }
        }
    }
    int* op = idxout + ((long long)b * GN + n) * 16;
#pragma unroll
    for (int i = 0; i < 16; ++i) op[i] = bidx[i];
}

// ---------------- e1 -> blocked layout ----------------
__global__ void e1_kernel(const float* __restrict__ pts, const float* __restrict__ W,
                          const float* __restrict__ g, const float* __restrict__ bb,
                          half_t* __restrict__ out)
{
    __shared__ float Wsh[768], gs[128], bs[128];
    int b = blockIdx.x, tid = threadIdx.x;
    int n = blockIdx.y * 256 + tid;
    for (int i = tid; i < 768; i += 256) Wsh[i] = W[i];
    if (tid < 128) { gs[tid] = g[tid]; bs[tid] = bb[tid]; }
    __syncthreads();
    float x[6];
#pragma unroll
    for (int c = 0; c < 6; ++c) x[c] = pts[((long long)b * 6 + c) * GN + n];
    for (int c8 = 0; c8 < 128; c8 += 8) {
        __align__(16) half_t h8[8];
#pragma unroll
        for (int q = 0; q < 8; ++q) {
            int o = c8 + q;
            float s = 0.f;
#pragma unroll
            for (int c = 0; c < 6; ++c) s += Wsh[o * 6 + c] * x[c];
            s = fmaxf(s * gs[o] + bs[o], 0.f);
            h8[q] = __float2half_rn(s);
        }
        int cb = c8 >> 6;
        int gpos = ((c8 >> 3) & 7) ^ (n & 7);
        *(uint4*)(out + (((size_t)b * 2 + cb) * GN + n) * 64 + gpos * 8) = *(uint4*)h8;
    }
}

// ---------------- GEMM: bulk-fed, 128n x 64o tiles, 3-stage, 3 CTAs/SM --------
struct GemmArgs {
    const half_t* Wp;
    int O, K;
    const half_t* Bx; int aCb, aCbOff;
    half_t* Y; int yCbTot, yCbOff;
    float* oF; int oFC;
    const float *pre, *g, *post, *postB;
    const half_t* R; int rCbTot, rCbOff;
    float *pMX, *pSM;       // per-tile max/sum partials (Wf only)
    int act;
};

__device__ __forceinline__ uint32_t s2u(const void* p) {
    return (uint32_t)__cvta_generic_to_shared(p);
}
__device__ __forceinline__ void ldm4(uint32_t* r, uint32_t a) {
    asm volatile("ldmatrix.sync.aligned.m8n8.x4.shared.b16 {%0,%1,%2,%3},[%4];\n"
                 : "=r"(r[0]), "=r"(r[1]), "=r"(r[2]), "=r"(r[3]) : "r"(a));
}
__device__ __forceinline__ void mma16816(float* d, const uint32_t* A, uint32_t b0, uint32_t b1) {
    asm volatile(
        "mma.sync.aligned.m16n8k16.row.col.f32.f16.f16.f32 "
        "{%0,%1,%2,%3},{%4,%5,%6,%7},{%8,%9},{%0,%1,%2,%3};\n"
        : "+f"(d[0]), "+f"(d[1]), "+f"(d[2]), "+f"(d[3])
        : "r"(A[0]), "r"(A[1]), "r"(A[2]), "r"(A[3]), "r"(b0), "r"(b1));
}
__device__ __forceinline__ void wait_par(uint32_t mbar, int ph) {
    asm volatile(
        "{\n\t.reg .pred P1;\n\tWL_%=:\n\t"
        "mbarrier.try_wait.parity.acquire.cta.shared::cta.b64 P1,[%0],%1,0x989680;\n\t"
        "@P1 bra WD_%=;\n\tbra WL_%=;\n\tWD_%=:\n\t}"
        :: "r"(mbar), "r"((uint32_t)ph) : "memory");
}
__device__ __forceinline__ void bulk_ld(uint32_t dst, const void* src, uint32_t bytes, uint32_t mbar) {
    asm volatile("cp.async.bulk.shared::cluster.global.mbarrier::complete_tx::bytes [%0],[%1],%2,[%3];\n"
                 :: "r"(dst), "l"(src), "r"(bytes), "r"(mbar) : "memory");
}
__device__ __forceinline__ void bulk_st(void* dst, uint32_t src, uint32_t bytes) {
    asm volatile("cp.async.bulk.global.shared::cta.bulk_group [%0],[%1],%2;\n"
                 :: "l"(dst), "r"(src), "r"(bytes) : "memory");
}

// smem: [0..1024) ctrl, then 3 stages x 24KB (ACT 16KB + WT 8KB)
#define STG_BYTES 24576
#define SMEM_GEMM (1024 + 3 * STG_BYTES)

__global__ void __launch_bounds__(256, 3) gemm_mma(GemmArgs P)
{
    extern __shared__ char sm[];
    const uint32_t smb = s2u(sm);
    const int tid = threadIdx.x, lane = tid & 31, wid = tid >> 5;
    const int wn = wid & 3, wo = wid >> 2;       // warp tile: 32n x 32o
    const int b = blockIdx.z, n0 = blockIdx.x * 128, o0 = blockIdx.y * 64;
    const int nch = P.K >> 6;

    if (tid == 0) {
#pragma unroll
        for (int s = 0; s < 3; ++s)
            asm volatile("mbarrier.init.shared.b64 [%0],1;" :: "r"(smb + s * 8) : "memory");
    }
    __syncthreads();

    auto issueChunk = [&](int c) {
        if (tid == 0) {
            int s = c % 3;
            uint32_t mbar = smb + s * 8;
            asm volatile("mbarrier.arrive.expect_tx.shared.b64 _,[%0],%1;"
                         :: "r"(mbar), "r"((uint32_t)STG_BYTES) : "memory");
            uint32_t st = smb + 1024 + s * STG_BYTES;
            const half_t* asrc = P.Bx + (((size_t)b * P.aCb + P.aCbOff + c) * GN + n0) * 64;
            bulk_ld(st, asrc, 16384, mbar);
            const half_t* wsrc = P.Wp + ((size_t)blockIdx.y * nch + c) * 4096;
            bulk_ld(st + 16384, wsrc, 8192, mbar);
        }
    };

    float acc[2][4][4];
#pragma unroll
    for (int i = 0; i < 2; ++i)
#pragma unroll
        for (int j = 0; j < 4; ++j)
#pragma unroll
            for (int k = 0; k < 4; ++k) acc[i][j][k] = 0.f;

    issueChunk(0);
    if (nch > 1) issueChunk(1);
    if (nch > 2) issueChunk(2);

    const int rowIn16 = (lane & 7) + ((lane >> 3) & 1) * 8;
    const int colB = (lane >> 4) << 4;
    int ph[3] = {0, 0, 0};

    for (int c = 0; c < nch; ++c) {
        int s = c % 3;
        wait_par(smb + s * 8, ph[s]);
        ph[s] ^= 1;
        uint32_t actB = smb + 1024 + s * STG_BYTES;
        uint32_t wtB = actB + 16384;
#pragma unroll
        for (int ks = 0; ks < 4; ++ks) {
            uint32_t bw[2][4];
#pragma unroll
            for (int j = 0; j < 2; ++j) {
                int row = wo * 32 + j * 16 + rowIn16;
                ldm4(bw[j], wtB + (uint32_t)(row * 128 + swz(row, ks * 32 + colB)));
            }
#pragma unroll
            for (int mt = 0; mt < 2; ++mt) {
                uint32_t aF[4];
                int row = wn * 32 + mt * 16 + rowIn16;
                ldm4(aF, actB + (uint32_t)(row * 128 + swz(row, ks * 32 + colB)));
#pragma unroll
                for (int j = 0; j < 2; ++j) {
                    mma16816(acc[mt][2 * j],     aF, bw[j][0], bw[j][2]);
                    mma16816(acc[mt][2 * j + 1], aF, bw[j][1], bw[j][3]);
                }
            }
        }
        __syncthreads();
        if (c + 3 < nch) issueChunk(c + 3);
    }

    // ---- epilogue ----
    const int q = lane >> 2, tcol = (lane & 3) * 2;
    half_t* sY = (half_t*)(sm + 1024);            // 16KB fp16 staging
    float*  sF = (float*)(sm + 1024);             // 32KB fp32 staging (out GEMM)

#pragma unroll
    for (int mt = 0; mt < 2; ++mt) {
#pragma unroll
        for (int ot = 0; ot < 4; ++ot) {
            int ol = wo * 32 + ot * 8 + tcol;
            int o = o0 + ol;
            bool ok = (o < P.O);
            float pr0 = 0, pr1 = 0, g0 = 1, g1 = 1, po0 = 0, po1 = 0;
            if (ok) {
                if (P.pre) { pr0 = P.pre[o]; pr1 = P.pre[o + 1]; }
                if (P.g) { g0 = P.g[o]; g1 = P.g[o + 1]; }
                if (P.post) { po0 = P.post[o]; po1 = P.post[o + 1]; }
                if (P.postB) { po0 += P.postB[b * P.O + o]; po1 += P.postB[b * P.O + o + 1]; }
            }
#pragma unroll
            for (int hh = 0; hh < 2; ++hh) {
                int nl = wn * 32 + mt * 16 + q + hh * 8;
                int n = n0 + nl;
                float v0 = (acc[mt][ot][hh * 2 + 0] + pr0) * g0 + po0;
                float v1 = (acc[mt][ot][hh * 2 + 1] + pr1) * g1 + po1;
                if (P.R) {
                    int och = o0 + ol;
                    size_t rrow = ((size_t)b * P.rCbTot + P.rCbOff + (och >> 6)) * GN + n;
                    int ci = och & 63;
                    const __half2 r2 = *(const __half2*)(P.R + rrow * 64 + (swz(n, ci * 2) >> 1));
                    float2 rf = __half22float2(r2);
                    v0 += rf.x; v1 += rf.y;
                }
                if (P.act == 1) { v0 = fmaxf(v0, 0.f); v1 = fmaxf(v1, 0.f); }
                else if (P.act == 2) { v0 = v0 > 0.f ? v0 : 0.2f * v0; v1 = v1 > 0.f ? v1 : 0.2f * v1; }
                if (P.Y) {
                    __half2 hp = __floats2half2_rn(v0, v1);
                    *(__half2*)(sY + nl * 64 + (swz(nl, ol * 2) >> 1)) = hp;
                }
                if (P.oF && ok) {
                    sF[ol * 128 + nl] = v0;
                    if (o + 1 < P.O) sF[(ol + 1) * 128 + nl] = v1;
                }
            }
        }
    }
    if (P.Y) {
        __syncthreads();
        asm volatile("fence.proxy.async.shared::cta;" ::: "memory");
        if (tid == 0) {
            bulk_st(P.Y + (((size_t)b * P.yCbTot + P.yCbOff + (o0 >> 6)) * GN + n0) * 64,
                    s2u(sY), 16384);
            asm volatile("cp.async.bulk.commit_group;\n" ::: "memory");
            asm volatile("cp.async.bulk.wait_group 0;\n" ::: "memory");
        }
        if (P.pMX && tid < 32) {
            // per-tile max/sum over the 128 points for channel pair (2*tid, 2*tid+1)
            float mx0 = -3.4e38f, mx1 = -3.4e38f, s0 = 0.f, s1 = 0.f;
            for (int nl = 0; nl < 128; ++nl) {
                __half2 hv = *(__half2*)(sY + nl * 64 + (swz(nl, tid * 4) >> 1));
                float2 f = __half22float2(hv);
                mx0 = fmaxf(mx0, f.x); mx1 = fmaxf(mx1, f.y);
                s0 += f.x; s1 += f.y;
            }
            size_t o = ((size_t)(b * 16 + blockIdx.x)) * 1024 + o0 + tid * 2;
            P.pMX[o] = mx0; P.pMX[o + 1] = mx1;
            P.pSM[o] = s0;  P.pSM[o + 1] = s1;
        }
    }
    if (P.oF) {
        __syncthreads();
        asm volatile("fence.proxy.async.shared::cta;" ::: "memory");
        if (tid == 0) {
            for (int o = 0; o < P.O; ++o)
                bulk_st(P.oF + ((size_t)b * P.oFC + o) * GN + n0,
                        s2u(sm + 1024) + o * 512, 512);
            asm volatile("cp.async.bulk.commit_group;\n" ::: "memory");
            asm volatile("cp.async.bulk.wait_group 0;\n" ::: "memory");
        }
    }
}

// ---------------- gather + max (T blocked -> M blocked) ----------------
__global__ void gathermax_kernel(const half_t* __restrict__ T, const int* __restrict__ IDX,
                                 half_t* __restrict__ M)
{
    int b = blockIdx.x;
    int w = threadIdx.x >> 5, l = threadIdx.x & 31;
    int n = blockIdx.y * 8 + w;
    const int* ib = IDX + ((size_t)b * GN + n) * 16;
    int ch0 = l * 4, cb = ch0 >> 6, ci = ch0 & 63;
    const half_t* tb = T + ((size_t)b * 2 + cb) * GN * 64;
    float4 best = make_float4(-3.4e38f, -3.4e38f, -3.4e38f, -3.4e38f);
#pragma unroll
    for (int k = 0; k < 16; ++k) {
        int j = ib[k];
        uint2 u = *(const uint2*)(tb + (size_t)j * 64 + (swz(j, ci * 2) >> 1));
        float2 a = __half22float2(*(__half2*)&u.x);
        float2 c = __half22float2(*(__half2*)&u.y);
        best.x = fmaxf(best.x, a.x); best.y = fmaxf(best.y, a.y);
        best.z = fmaxf(best.z, c.x); best.w = fmaxf(best.w, c.y);
    }
    __align__(8) half_t h4[4];
    h4[0] = __float2half_rn(best.x); h4[1] = __float2half_rn(best.y);
    h4[2] = __float2half_rn(best.z); h4[3] = __float2half_rn(best.w);
    *(uint2*)(M + (((size_t)b * 2 + cb) * GN + n) * 64 + (swz(n, ci * 2) >> 1)) = *(uint2*)h4;
}

// ---------------- combine per-tile partials -> RMAX/RAVG ----------------
__global__ void reduce2_kernel(const float* __restrict__ PMX, const float* __restrict__ PSM,
                               float* __restrict__ RMAX, float* __restrict__ RAVG)
{
    int b = blockIdx.x;
    int c = blockIdx.y * 256 + threadIdx.x;
    float mx = -3.4e38f, s = 0.f;
#pragma unroll
    for (int g = 0; g < 16; ++g) {
        size_t o = ((size_t)(b * 16 + g)) * 1024 + c;
        mx = fmaxf(mx, PMX[o]); s += PSM[o];
    }
    RMAX[b * 1024 + c] = mx;
    RAVG[b * 1024 + c] = s * (1.f / GN);
}

// ---------------- per-batch bias for c1 ----------------
__global__ void bias1_kernel(const float* __restrict__ Wc1, const float* __restrict__ bc1,
                             const float* __restrict__ gc1, const float* __restrict__ bb1,
                             const float* __restrict__ Wl, const float* __restrict__ gl,
                             const float* __restrict__ bl, const float* __restrict__ label,
                             const float* __restrict__ RMAX, const float* __restrict__ RAVG,
                             float* __restrict__ B1)
{
    int b = blockIdx.x;
    int tid = threadIdx.x, warp = tid >> 5, lane = tid & 31;
    __shared__ float lab[64];
    if (tid < 64) {
        float s = 0.f;
#pragma unroll
        for (int i = 0; i < 16; ++i) s += Wl[tid * 16 + i] * label[b * 16 + i];
        s = s * gl[tid] + bl[tid];
        lab[tid] = s > 0.f ? s : 0.2f * s;
    }
    __syncthreads();
    int o = blockIdx.y * 8 + warp;
    const float* wr = Wc1 + (long long)o * 3136;
    const float* xm = RMAX + b * 1024;
    const float* xa = RAVG + b * 1024;
    float s = 0.f;
    for (int j = lane; j < 1024; j += 32)
        s += wr[1024 + j] * xm[j] + wr[2048 + j] * xa[j];
    for (int j = lane; j < 64; j += 32)
        s += wr[3072 + j] * lab[j];
#pragma unroll
    for (int off = 16; off; off >>= 1) s += __shfl_xor_sync(0xffffffffu, s, off);
    if (!lane) B1[b * 512 + o] = gc1[o] * (s + bc1[o]) + bb1[o];
}

// ---------------- host ----------------
template <class T>
static T* symp(const void* s) { void* p = nullptr; cudaGetSymbolAddress(&p, s); return (T*)p; }

static void run_gemm(const half_t* Wp, int O, int K,
                     const half_t* Bx, int aCb, int aCbOff,
                     half_t* Y, int yCbTot, int yCbOff,
                     float* oF, int oFC,
                     const float* pre, const float* g, const float* post, const float* postB,
                     const half_t* R, int rCbTot, int rCbOff,
                     float* pMX, float* pSM, int act)
{
    GemmArgs a;
    a.Wp = Wp; a.O = O; a.K = K; a.Bx = Bx; a.aCb = aCb; a.aCbOff = aCbOff;
    a.Y = Y; a.yCbTot = yCbTot; a.yCbOff = yCbOff;
    a.oF = oF; a.oFC = oFC;
    a.pre = pre; a.g = g; a.post = post; a.postB = postB;
    a.R = R; a.rCbTot = rCbTot; a.rCbOff = rCbOff;
    a.pMX = pMX; a.pSM = pSM; a.act = act;
    dim3 grid(GN / 128, (O + 63) / 64, GB);
    gemm_mma<<<grid, 256, SMEM_GEMM>>>(a);
}

extern "C" void kernel_launch(void* const* d_in, const int* in_sizes, int n_in,
                              void* d_out, int out_size)
{
#define FIN(i) ((const float*)d_in[i])
    const float *pts = FIN(0), *label = FIN(1), *We1 = FIN(2), *ge1 = FIN(3), *be1 = FIN(4),
                *We2 = FIN(5), *ge2 = FIN(6), *be2 = FIN(7), *W1 = FIN(8), *g1 = FIN(9),
                *b1 = FIN(10), *W2 = FIN(11), *g2 = FIN(12), *b2 = FIN(13), *Wf = FIN(14),
                *gf = FIN(15), *bf_ = FIN(16), *Wl = FIN(17), *gl = FIN(18), *bl = FIN(19),
                *Wc1 = FIN(20), *bc1 = FIN(21), *gc1 = FIN(22), *bb1 = FIN(23), *Wc2 = FIN(24),
                *bc2 = FIN(25), *gc2 = FIN(26), *bb2 = FIN(27), *Wc3 = FIN(28), *bc3 = FIN(29);
#undef FIN
    float* out = (float*)d_out;

    cudaFuncSetAttribute(gemm_mma, cudaFuncAttributeMaxDynamicSharedMemorySize, SMEM_GEMM);

    half_t *E1 = symp<half_t>(g_E1), *H = symp<half_t>(g_H), *M = symp<half_t>(g_M);
    half_t *T = symp<half_t>(g_T), *XC = symp<half_t>(g_XC), *XF = symp<half_t>(g_XF);
    half_t *C1 = symp<half_t>(g_C1), *C2 = symp<half_t>(g_C2);
    float *RMAX = symp<float>(g_RMAX), *RAVG = symp<float>(g_RAVG), *B1 = symp<float>(g_B1);
    float *PMX = symp<float>(g_PMX), *PSM = symp<float>(g_PSM);
    int* IDX = symp<int>(g_IDX);
    half_t *hWe2 = symp<half_t>(g_We2), *hW1 = symp<half_t>(g_W1), *hW2 = symp<half_t>(g_W2);
    half_t *hWf = symp<half_t>(g_Wf), *hWc1 = symp<half_t>(g_Wc1);
    half_t *hWc2 = symp<half_t>(g_Wc2), *hWc3 = symp<half_t>(g_Wc3);

    // launch 0: KNN
    knn_kernel<<<dim3(GB, GN / 128), 128>>>(pts, IDX);
    // launch 1: e1
    e1_kernel<<<dim3(GB, GN / 256), 256>>>(pts, We1, ge1, be1, E1);
    // launch 2: weight conversion (64-row blocks)
    {
        CwArgs a{};
        a.s[0] = {We2, hWe2, 128, 128, 128, 2, 0};
        a.s[1] = {W1,  hW1,  384, 128, 128, 2, 4};
        a.s[2] = {W2,  hW2,  384, 128, 128, 2, 16};
        a.s[3] = {Wf,  hWf, 1024, 384, 384, 6, 28};
        a.s[4] = {Wc1, hWc1, 512, 1024, 3136, 16, 124};
        a.s[5] = {Wc2, hWc2, 256, 512, 512, 8, 252};
        a.s[6] = {Wc3, hWc3, 50, 256, 256, 4, 284};
        a.totalBlks = 288;
        convw_blk<<<(288 * 4096 + 255) / 256, 256>>>(a);
    }
    // launch 3: e2 GEMM  <-- ncu capture slot
    run_gemm(hWe2, 128, 128, E1, 2, 0, H, 2, 0, nullptr, 0,
             nullptr, ge2, be2, nullptr, nullptr, 0, 0, nullptr, nullptr, 1);

    // three edge blocks
    const half_t* h = H;
    int hCb = 2, hOff = 0;
    for (int i = 0; i < 3; ++i) {
        run_gemm(hW1 + (size_t)i * 16384, 128, 128, h, hCb, hOff,
                 T, 2, 0, nullptr, 0,
                 nullptr, g1 + i * 128, b1 + i * 128, nullptr, nullptr, 0, 0,
                 nullptr, nullptr, 1);
        gathermax_kernel<<<dim3(GB, GN / 8), 256>>>(T, IDX, M);
        run_gemm(hW2 + (size_t)i * 16384, 128, 128, M, 2, 0,
                 XC, 6, i * 2, nullptr, 0,
                 nullptr, g2 + i * 128, b2 + i * 128, nullptr, h, hCb, hOff,
                 nullptr, nullptr, 1);
        h = XC; hCb = 6; hOff = i * 2;
    }

    // xf = leaky(bn(Wf @ xcat)) + fused per-tile max/sum partials
    run_gemm(hWf, 1024, 384, XC, 6, 0, XF, 16, 0, nullptr, 0,
             nullptr, gf, bf_, nullptr, nullptr, 0, 0, PMX, PSM, 2);

    // combine partials + per-batch bias
    reduce2_kernel<<<dim3(GB, 4), 256>>>(PMX, PSM, RMAX, RAVG);
    bias1_kernel<<<dim3(GB, 64), 256>>>(Wc1, bc1, gc1, bb1, Wl, gl, bl, label,
                                        RMAX, RAVG, B1);

    // c1 = relu(gc1 * Wc1[:, :1024]@xf + per-batch bias)
    run_gemm(hWc1, 512, 1024, XF, 16, 0, C1, 8, 0, nullptr, 0,
             nullptr, gc1, nullptr, B1, nullptr, 0, 0, nullptr, nullptr, 1);
    // c2 = relu((Wc2@c1 + bc2)*gc2 + bb2)
    run_gemm(hWc2, 256, 512, C1, 8, 0, C2, 4, 0, nullptr, 0,
             bc2, gc2, bb2, nullptr, nullptr, 0, 0, nullptr, nullptr, 1);
    // out = Wc3@c2 + bc3  (fp32 staged + bulk stores)
    run_gemm(hWc3, 50, 256, C2, 4, 0, nullptr, 0, 0, out, 50,
             bc3, nullptr, nullptr, nullptr, nullptr, 0, 0, nullptr, nullptr, 0);
}